// round 17
// baseline (speedup 1.0000x reference)
#include <cuda_runtime.h>
#include <cuda_fp16.h>
#include <cstdint>
#include <math.h>

#define NTOK 16384
#define DIM  4096
#define NE   64
#define BT   64                   // tokens per CTA: 4 m16 stripes
#define KT   32                   // K per chunk (2 k16 halves across warps)
#define NCH  (DIM / KT)           // 128
#define NTHR 256                  // 8 warps: 4 stripes x 2 khalf
#define WARR 4096                 // per-chunk bytes per array (hi / lo)
#define WB   8192                 // per-chunk packed W bytes
#define WSEC 256                  // per-(khalf,qid) section bytes: 8 slots x 32B
#define SCSTR 66

// split: hi = rz-f16 pack, lo = rz-f16(x - mask(x)).
static __device__ __forceinline__ void split_pair(float f0, float f1,
                                                  uint32_t& hi2, uint32_t& lo2) {
    asm("cvt.rz.f16x2.f32 %0, %1, %2;" : "=r"(hi2) : "f"(f1), "f"(f0));
    const float m0 = __uint_as_float(__float_as_uint(f0) & 0xffffe000u);
    const float m1 = __uint_as_float(__float_as_uint(f1) & 0xffffe000u);
    const float r0 = f0 - m0, r1 = f1 - m1;
    asm("cvt.rz.f16x2.f32 %0, %1, %2;" : "=r"(lo2) : "f"(r1), "f"(r0));
}
static __device__ __forceinline__ void mma16(float* c, const uint32_t* a,
                                             uint32_t b0, uint32_t b1) {
    asm volatile(
        "mma.sync.aligned.m16n8k16.row.col.f32.f16.f16.f32 "
        "{%0,%1,%2,%3}, {%4,%5,%6,%7}, {%8,%9}, {%0,%1,%2,%3};"
        : "+f"(c[0]), "+f"(c[1]), "+f"(c[2]), "+f"(c[3])
        : "r"(a[0]), "r"(a[1]), "r"(a[2]), "r"(a[3]), "r"(b0), "r"(b1));
}

// Packed, pre-split W. Per chunk: [arr 2][khalf 2][qid 8][slot 8][nt-word 8].
// Section (khalf,qid) = 8 slots x 32B = 256B. Slot v holds k = chunk*32 +
// khalf*16 + 2v, 2v+1; word nt = expert nt*8 + qid.
// Lane (khalf,qid,qt) reads its fragment (slots 2qt, 2qt+1) as 64B contiguous.
__device__ __align__(16) char g_wpack[NCH * WB];

__global__ void pack_w_kernel(const float* __restrict__ W) {
    const int i = blockIdx.x * blockDim.x + threadIdx.x;   // 131072
    if (i >= NE * NCH * 16) return;
    const int g     = i & 15;                 // k-pair within chunk
    const int chunk = (i >> 4) & (NCH - 1);
    const int e     = i >> 11;
    const int qid   = e & 7, nt = e >> 3;
    const int kh    = g >> 3, v = g & 7;
    const int k0    = chunk * KT + 2 * g;
    const float w0 = W[(size_t)e * DIM + k0];
    const float w1 = W[(size_t)e * DIM + k0 + 1];
    const __half h0 = __float2half_rn(w0), h1 = __float2half_rn(w1);
    const __half l0 = __float2half_rn(w0 - __half2float(h0));
    const __half l1 = __float2half_rn(w1 - __half2float(h1));
    const uint32_t hi = ((uint32_t)__half_as_ushort(h1) << 16) | __half_as_ushort(h0);
    const uint32_t lo = ((uint32_t)__half_as_ushort(l1) << 16) | __half_as_ushort(l0);
    const uint32_t base = (uint32_t)chunk * WB + (uint32_t)(kh * 8 + qid) * WSEC
                        + v * 32 + nt * 4;
    *(uint32_t*)(g_wpack + base)        = hi;
    *(uint32_t*)(g_wpack + base + WARR) = lo;
}

__global__ __launch_bounds__(NTHR, 2)
void gating_mma(const float* __restrict__ X, const float* __restrict__ B,
                float* __restrict__ out, int voff)
{
    __shared__ float SC[2][BT * SCSTR];
    const int tid    = threadIdx.x;
    const int wid    = tid >> 5;
    const int lane   = tid & 31;
    const int qid    = lane >> 2;
    const int qt     = lane & 3;
    const int stripe = wid & 3;          // m16 stripe
    const int khalf  = wid >> 2;         // k16 half of each chunk
    const int token0 = blockIdx.x * BT;

    // A: one float4 per row per chunk, rows qid and qid+8 of this stripe
    const float* ap0 = X + (size_t)(token0 + stripe * 16 + qid) * DIM
                     + khalf * 16 + qt * 4;
    const float* ap1 = ap0 + (size_t)8 * DIM;
    // B: lane fragment base in packed W
    const char* bp = g_wpack + (uint32_t)(khalf * 8 + qid) * WSEC + qt * 64;

    float acc[8][4];
    #pragma unroll
    for (int nt = 0; nt < 8; nt++)
        #pragma unroll
        for (int j = 0; j < 4; j++) acc[nt][j] = 0.f;

    auto body = [&](const float4& f0, const float4& f1, const uint4* h,
                    const char* lop) {
        // issue lo loads first (consumed in the last MMA group)
        const uint4 l0 = *(const uint4*)(lop);
        const uint4 l1 = *(const uint4*)(lop + 16);
        const uint4 l2 = *(const uint4*)(lop + 32);
        const uint4 l3 = *(const uint4*)(lop + 48);

        uint32_t ah[4], al[4];
        split_pair(f0.x, f0.y, ah[0], al[0]);   // rows qid / k pair (4qt,4qt+1)
        split_pair(f1.x, f1.y, ah[1], al[1]);   // row qid+8
        split_pair(f0.z, f0.w, ah[2], al[2]);   // k pair (4qt+2,4qt+3)
        split_pair(f1.z, f1.w, ah[3], al[3]);

        const uint32_t h0w[4] = {h[0].x, h[0].y, h[0].z, h[0].w};
        const uint32_t h1w[4] = {h[1].x, h[1].y, h[1].z, h[1].w};
        const uint32_t h2w[4] = {h[2].x, h[2].y, h[2].z, h[2].w};
        const uint32_t h3w[4] = {h[3].x, h[3].y, h[3].z, h[3].w};

        #pragma unroll
        for (int nt = 0; nt < 4; nt++) mma16(acc[nt],     ah, h0w[nt], h2w[nt]); // hh
        #pragma unroll
        for (int nt = 0; nt < 4; nt++) mma16(acc[nt + 4], ah, h1w[nt], h3w[nt]);
        #pragma unroll
        for (int nt = 0; nt < 4; nt++) mma16(acc[nt],     al, h0w[nt], h2w[nt]); // lh
        #pragma unroll
        for (int nt = 0; nt < 4; nt++) mma16(acc[nt + 4], al, h1w[nt], h3w[nt]);

        const uint32_t l0w[4] = {l0.x, l0.y, l0.z, l0.w};
        const uint32_t l1w[4] = {l1.x, l1.y, l1.z, l1.w};
        const uint32_t l2w[4] = {l2.x, l2.y, l2.z, l2.w};
        const uint32_t l3w[4] = {l3.x, l3.y, l3.z, l3.w};
        #pragma unroll
        for (int nt = 0; nt < 4; nt++) mma16(acc[nt],     ah, l0w[nt], l2w[nt]); // hl
        #pragma unroll
        for (int nt = 0; nt < 4; nt++) mma16(acc[nt + 4], ah, l1w[nt], l3w[nt]);
    };

    // ---- prologue: set A = chunk 0 ----
    float4 fa0 = *(const float4*)(ap0);
    float4 fa1 = *(const float4*)(ap1);
    uint4 ha[4];
    {
        const char* p = bp;
        ha[0] = *(const uint4*)(p);      ha[1] = *(const uint4*)(p + 16);
        ha[2] = *(const uint4*)(p + 32); ha[3] = *(const uint4*)(p + 48);
    }

    #pragma unroll 1
    for (int c = 0; c < NCH; c += 2) {
        // prefetch chunk c+1 into set B
        float4 fb0 = *(const float4*)(ap0 + (c + 1) * KT);
        float4 fb1 = *(const float4*)(ap1 + (c + 1) * KT);
        uint4 hb[4];
        {
            const char* p = bp + (size_t)(c + 1) * WB;
            hb[0] = *(const uint4*)(p);      hb[1] = *(const uint4*)(p + 16);
            hb[2] = *(const uint4*)(p + 32); hb[3] = *(const uint4*)(p + 48);
        }

        body(fa0, fa1, ha, bp + (size_t)c * WB + WARR);

        // prefetch chunk c+2 into set A (clamped; harmless reload at tail)
        const int cn = (c + 2 < NCH) ? c + 2 : NCH - 1;
        fa0 = *(const float4*)(ap0 + cn * KT);
        fa1 = *(const float4*)(ap1 + cn * KT);
        {
            const char* p = bp + (size_t)cn * WB;
            ha[0] = *(const uint4*)(p);      ha[1] = *(const uint4*)(p + 16);
            ha[2] = *(const uint4*)(p + 32); ha[3] = *(const uint4*)(p + 48);
        }

        body(fb0, fb1, hb, bp + (size_t)(c + 1) * WB + WARR);
    }

    // ---- scores -> khalf partial banks (bias fused into bank 0) ----
    {
        float* r0 = &SC[khalf][(stripe * 16 + qid) * SCSTR];
        float* r1 = r0 + 8 * SCSTR;
        #pragma unroll
        for (int nt = 0; nt < 8; nt++) {
            const int cb = nt * 8 + qt * 2;
            const float b0 = khalf ? 0.f : __ldg(B + cb);
            const float b1 = khalf ? 0.f : __ldg(B + cb + 1);
            *(float2*)(r0 + cb) = make_float2(acc[nt][0] + b0, acc[nt][1] + b1);
            *(float2*)(r1 + cb) = make_float2(acc[nt][2] + b0, acc[nt][3] + b1);
        }
    }
    __syncthreads();

    if (tid < BT) {
        const float* row0 = &SC[0][tid * SCSTR];
        const float* row1 = &SC[1][tid * SCSTR];

        float sc[NE];
        #pragma unroll
        for (int e = 0; e < NE; e++) sc[e] = row0[e] + row1[e];

        float m = sc[0];
        #pragma unroll
        for (int e = 1; e < NE; e++) m = fmaxf(m, sc[e]);

        float se = 0.f;
        #pragma unroll
        for (int e = 0; e < NE; e++) se += __expf(sc[e] - m);

        float v1 = -1e30f, v2 = -1e30f; int i1 = -1, i2 = -1;
        #pragma unroll
        for (int e = 0; e < NE; e++) {
            const float s = sc[e];
            if (s > v1)      { v2 = v1; i2 = i1; v1 = s; i1 = e; }
            else if (s > v2) { v2 = s; i2 = e; }
        }

        const int g = token0 + tid;
        const float inv = 1.0f / se;
        out[g * 2 + 0]        = (float)i1;
        out[g * 2 + 1]        = (float)i2;
        out[voff + g * 2 + 0] = __expf(v1 - m) * inv;
        out[voff + g * 2 + 1] = __expf(v2 - m) * inv;
    }
}

extern "C" void kernel_launch(void* const* d_in, const int* in_sizes, int n_in,
                              void* d_out, int out_size) {
    const float* x = (const float*)d_in[0];
    const float* W = (const float*)d_in[1];
    const float* b = (const float*)d_in[2];
    float* out = (float*)d_out;

    pack_w_kernel<<<(NE * NCH * 16 + 255) / 256, 256>>>(W);
    gating_mma<<<NTOK / BT, NTHR>>>(x, b, out, out_size / 2);
}